// round 10
// baseline (speedup 1.0000x reference)
#include <cuda_runtime.h>
#include <cuda_fp16.h>
#include <cstdint>

// ---------------------------------------------------------------------------
// Geometry
// ---------------------------------------------------------------------------
#define IN_F    2048
#define OUT_F   2048
#define N_NODES 65536
#define NKSLABS 32                       // K consumed in 64-half slabs
#define A_BLK   16384                    // 128 rows x 128B (64 halves)
#define B_BLK   32768                    // 256 rows x 128B
#define STAGES  4
#define STAGE_BYTES (A_BLK + B_BLK)      // 49152
#define SMEM_BYTES  (STAGES * STAGE_BYTES + 2048)

// ---------------------------------------------------------------------------
// Device scratch (allocation-free rule: static globals)
// ---------------------------------------------------------------------------
__device__ __align__(1024) unsigned char g_Wt[8 * NKSLABS * B_BLK];                 // 8 MB fp16 W, tiled+swizzled
__device__ __align__(1024) unsigned char g_Xt[(size_t)512 * NKSLABS * A_BLK];       // 256 MB fp16 x, tiled+swizzled

// ---------------------------------------------------------------------------
// PTX helpers (baseline PTX only)
// ---------------------------------------------------------------------------
__device__ __forceinline__ uint32_t smem_to_u32(const void* p) {
    uint32_t a;
    asm("{ .reg .u64 t; cvta.to.shared.u64 t, %1; cvt.u32.u64 %0, t; }" : "=r"(a) : "l"(p));
    return a;
}
#define MBARRIER_INIT(addr, cnt) \
    asm volatile("mbarrier.init.shared.b64 [%0], %1;" :: "r"((uint32_t)(addr)), "r"((uint32_t)(cnt)) : "memory")
#define MBARRIER_EXPECT_TX(addr, bytes) \
    asm volatile("mbarrier.arrive.expect_tx.shared.b64 _, [%0], %1;" :: "r"((uint32_t)(addr)), "r"((uint32_t)(bytes)) : "memory")
#define MBARRIER_ARRIVE(addr) \
    asm volatile("mbarrier.arrive.shared.b64 _, [%0];" :: "r"((uint32_t)(addr)) : "memory")
#define MBARRIER_WAIT_PARITY(addr, parity) do {                                            \
    uint32_t _m = (uint32_t)(addr); uint32_t _p = (uint32_t)(parity); uint32_t _d;         \
    asm volatile("{\n\t.reg .pred p;\n\t"                                                  \
        "mbarrier.try_wait.parity.acquire.cta.shared::cta.b64 p, [%1], %2;\n\t"            \
        "selp.b32 %0, 1, 0, p;\n\t}" : "=r"(_d) : "r"(_m), "r"(_p) : "memory");            \
    if (!_d) {                                                                             \
        asm volatile("{\n\t.reg .pred P1;\n\t"                                             \
            "WL_%=:\n\t"                                                                   \
            "mbarrier.try_wait.parity.acquire.cta.shared::cta.b64 P1, [%0], %1, 0x989680;\n\t" \
            "@P1 bra.uni WD_%=;\n\tbra.uni WL_%=;\n\tWD_%=:\n\t}"                          \
            :: "r"(_m), "r"(_p) : "memory");                                               \
    }                                                                                      \
} while (0)
#define FENCE_PROXY_ASYNC_SHARED_CTA() asm volatile("fence.proxy.async.shared::cta;" ::: "memory")
#define BULK_G2S(dst_smem, src_gmem, nbytes, mbar) \
    asm volatile("cp.async.bulk.shared::cluster.global.mbarrier::complete_tx::bytes [%0], [%1], %2, [%3];" \
                 :: "r"((uint32_t)(dst_smem)), "l"(src_gmem), "r"((uint32_t)(nbytes)), \
                    "r"((uint32_t)(mbar)) : "memory")
#define LDSM_X4(r, addr) \
    asm volatile("ldmatrix.sync.aligned.m8n8.x4.shared.b16 {%0,%1,%2,%3}, [%4];" \
                 : "=r"((r)[0]), "=r"((r)[1]), "=r"((r)[2]), "=r"((r)[3]) : "r"(addr))

__device__ __forceinline__ void mma16816(float* c, const uint32_t* a, const uint32_t* b) {
    asm volatile("mma.sync.aligned.m16n8k16.row.col.f32.f16.f16.f32 "
        "{%0,%1,%2,%3}, {%4,%5,%6,%7}, {%8,%9}, {%0,%1,%2,%3};"
        : "+f"(c[0]), "+f"(c[1]), "+f"(c[2]), "+f"(c[3])
        : "r"(a[0]), "r"(a[1]), "r"(a[2]), "r"(a[3]), "r"(b[0]), "r"(b[1]));
}

__device__ __forceinline__ uint32_t swz128(uint32_t off) { return off ^ ((off >> 3) & 0x70); }

// ---------------------------------------------------------------------------
// Preprocessing
// ---------------------------------------------------------------------------
__global__ void zero_wt_kernel() {
    int i = blockIdx.x * blockDim.x + threadIdx.x;          // 524288 float4s
    reinterpret_cast<float4*>(g_Wt)[i] = make_float4(0.f, 0.f, 0.f, 0.f);
}

// Scatter COO directly into fp16 tiled/swizzled W (sum semantics for dups)
__global__ void scatter_kernel(const float* __restrict__ vals, const int* __restrict__ rows,
                               const int* __restrict__ cols, int nnz) {
    int i = blockIdx.x * blockDim.x + threadIdx.x;
    if (i >= nnz) return;
    int n = rows[i], k = cols[i];
    uint32_t nt = n >> 8, r = n & 255, ks = k >> 6, c = k & 63;
    size_t off = (size_t)(nt * NKSLABS + ks) * B_BLK + swz128(r * 128 + c * 2);
    atomicAdd(reinterpret_cast<__half*>(g_Wt + off), __float2half(vals[i]));
}

// x fp32 -> fp16 tiled/swizzled; 16B store per thread (8 halves)
__global__ void conv_x_kernel(const float* __restrict__ x) {
    size_t e8 = (size_t)blockIdx.x * blockDim.x + threadIdx.x;  // 16.7M x 8-elem chunks
    int m = (int)(e8 >> 8);                                     // 256 chunks per row
    int k = ((int)e8 & 255) << 3;
    float4 v0 = reinterpret_cast<const float4*>(x)[e8 * 2];
    float4 v1 = reinterpret_cast<const float4*>(x)[e8 * 2 + 1];
    union { __half2 h[4]; uint4 u; } pk;
    pk.h[0] = __floats2half2_rn(v0.x, v0.y);
    pk.h[1] = __floats2half2_rn(v0.z, v0.w);
    pk.h[2] = __floats2half2_rn(v1.x, v1.y);
    pk.h[3] = __floats2half2_rn(v1.z, v1.w);
    uint32_t mt = (uint32_t)m >> 7, r = m & 127, ks = (uint32_t)k >> 6, c = k & 63;
    size_t off = ((size_t)mt * NKSLABS + ks) * A_BLK + swz128(r * 128 + c * 2);
    *reinterpret_cast<uint4*>(g_Xt + off) = pk.u;
}

// ---------------------------------------------------------------------------
// GEMM: CTA 128(M) x 256(N), 288 threads:
//   warps 0-7: compute, warp tile 64x64 (grid 2M x 4N), cross-slab pipelined
//   warp 8 (lane 0): dedicated producer (CONS wait + expect_tx + bulk copies)
// ---------------------------------------------------------------------------
__global__ void __launch_bounds__(288, 1)
gemm_kernel(const float* __restrict__ bias, float* __restrict__ out) {
    extern __shared__ __align__(16) unsigned char smem[];
    const uint32_t smem_u = smem_to_u32(smem);
    const uint32_t FULL   = smem_u;                              // 4 x 8B
    const uint32_t CONS   = smem_u + 32;                         // 4 x 8B
    const uint32_t base1k = (smem_u + 64 + 1023u) & ~1023u;      // stage data, 1KB aligned

    const int tid = threadIdx.x;
    const int w = tid >> 5, lane = tid & 31;
    const int nsup = blockIdx.x;      // 0..7
    const int msup = blockIdx.y;      // 0..511

    if (tid == 0) {
        #pragma unroll
        for (int s = 0; s < STAGES; s++) {
            MBARRIER_INIT(FULL + 8 * s, 1);
            MBARRIER_INIT(CONS + 8 * s, 8);
        }
        FENCE_PROXY_ASYNC_SHARED_CTA();
    }
    __syncthreads();

    const unsigned char* Asrc = g_Xt + (size_t)msup * NKSLABS * A_BLK;
    const unsigned char* Bsrc = g_Wt + (size_t)nsup * NKSLABS * B_BLK;

    if (w == 8) {
        // ---------------- producer warp ----------------
        if (lane == 0) {
            #pragma unroll
            for (int s = 0; s < STAGES - 1; s++) {
                uint32_t sb = base1k + s * STAGE_BYTES;
                MBARRIER_EXPECT_TX(FULL + 8 * s, STAGE_BYTES);
                BULK_G2S(sb,         Asrc + (size_t)s * A_BLK, A_BLK, FULL + 8 * s);
                BULK_G2S(sb + A_BLK, Bsrc + (size_t)s * B_BLK, B_BLK, FULL + 8 * s);
            }
            for (int s2 = STAGES - 1; s2 < NKSLABS; s2++) {
                const int st2 = s2 & 3;
                const int k = s2 >> 2;
                if (k >= 1) MBARRIER_WAIT_PARITY(CONS + 8 * st2, (k - 1) & 1);
                uint32_t sb = base1k + st2 * STAGE_BYTES;
                MBARRIER_EXPECT_TX(FULL + 8 * st2, STAGE_BYTES);
                BULK_G2S(sb,         Asrc + (size_t)s2 * A_BLK, A_BLK, FULL + 8 * st2);
                BULK_G2S(sb + A_BLK, Bsrc + (size_t)s2 * B_BLK, B_BLK, FULL + 8 * st2);
            }
        }
        return;
    }

    // ---------------- compute warps ----------------
    const int wm = w >> 2, wn = w & 3;

    float acc[4][8][4];
    #pragma unroll
    for (int i = 0; i < 4; i++)
        #pragma unroll
        for (int j = 0; j < 8; j++)
            #pragma unroll
            for (int q = 0; q < 4; q++) acc[i][j][q] = 0.f;

    // ldmatrix per-lane address components
    const int jj = lane >> 3, r8 = lane & 7;
    const int a_row = (jj & 1) * 8 + r8;      // A: {m0-7,k0-7},{m8-15,k0-7},{m0-7,k8-15},{m8-15,k8-15}
    const int a_kb  = (jj >> 1) * 16;
    const int b_row = (jj >> 1) * 8 + r8;     // B: {n0-7,k0-7},{n0-7,k8-15},{n8-15,k0-7},{n8-15,k8-15}
    const int b_kb  = (jj & 1) * 16;
    const uint32_t a_base = (uint32_t)(wm * 64 + a_row) * 128 + a_kb;   // + ms*2048 + kk*32
    const uint32_t b_base = (uint32_t)(wn * 64 + b_row) * 128 + b_kb;   // + ng*2048 + kk*32

    uint32_t a[2][4][4], b[2][4];

    // slab-0 prologue
    MBARRIER_WAIT_PARITY(FULL + 0, 0);
    {
        const uint32_t Ast0 = base1k, Bst0 = base1k + A_BLK;
        #pragma unroll
        for (int ms = 0; ms < 4; ms++)
            LDSM_X4(a[0][ms], Ast0 + swz128(a_base + ms * 2048));
        LDSM_X4(b[0], Bst0 + swz128(b_base));
    }

    for (int s = 0; s < NKSLABS; s++) {
        const int st = s & 3;
        const uint32_t Ast = base1k + st * STAGE_BYTES;
        const uint32_t Bst = Ast + A_BLK;
        const int stn = (s + 1) & 3;
        const uint32_t AstN = base1k + stn * STAGE_BYTES;
        const uint32_t BstN = AstN + A_BLK;
        const int phN = ((s + 1) >> 2) & 1;
        const bool more = (s + 1 < NKSLABS);

        #pragma unroll
        for (int t = 0; t < 16; t++) {
            const int kk = t >> 2, ng = t & 3;
            const int cb = t & 1, ca = kk & 1;

            if (t < 15) {
                const int t1 = t + 1;
                LDSM_X4(b[cb ^ 1], Bst + swz128(b_base + (t1 & 3) * 2048 + (t1 >> 2) * 32));
            } else if (more) {
                // next-slab prologue (FULL[s+1] already waited at t==14)
                LDSM_X4(b[cb ^ 1], BstN + swz128(b_base));
                #pragma unroll
                for (int ms = 0; ms < 4; ms++)
                    LDSM_X4(a[0][ms], AstN + swz128(a_base + ms * 2048));
            }
            if (ng == 0 && kk < 3) {
                #pragma unroll
                for (int ms = 0; ms < 4; ms++)
                    LDSM_X4(a[ca ^ 1][ms], Ast + swz128(a_base + ms * 2048 + (kk + 1) * 32));
            }
            #pragma unroll
            for (int ms = 0; ms < 4; ms++) {
                mma16816(acc[ms][2 * ng],     a[ca][ms], b[cb]);
                mma16816(acc[ms][2 * ng + 1], a[ca][ms], b[cb] + 2);
            }
            if (t == 14 && more) {
                // wait with ~8 pending MMA groups still draining the tensor pipe
                MBARRIER_WAIT_PARITY(FULL + 8 * stn, phN);
            }
        }

        // this warp is done reading stage st (t==15 loads came from stage stn)
        if (lane == 0) MBARRIER_ARRIVE(CONS + 8 * st);
    }

    // ---- epilogue: acc + bias -> out ----
    const int g  = lane >> 2;
    const int cq = (lane & 3) * 2;
    const int n_cta = nsup * 256 + wn * 64;
    const int m_cta = msup * 128 + wm * 64;
    #pragma unroll
    for (int ms = 0; ms < 4; ms++) {
        const int m0 = m_cta + ms * 16 + g;
        #pragma unroll
        for (int ns = 0; ns < 8; ns++) {
            const int n = n_cta + ns * 8 + cq;
            const float2 bv = *reinterpret_cast<const float2*>(bias + n);
            float2 v0, v1;
            v0.x = acc[ms][ns][0] + bv.x; v0.y = acc[ms][ns][1] + bv.y;
            v1.x = acc[ms][ns][2] + bv.x; v1.y = acc[ms][ns][3] + bv.y;
            *reinterpret_cast<float2*>(out + (size_t)m0 * OUT_F + n)       = v0;
            *reinterpret_cast<float2*>(out + (size_t)(m0 + 8) * OUT_F + n) = v1;
        }
    }
}

// ---------------------------------------------------------------------------
// Host launch
// ---------------------------------------------------------------------------
extern "C" void kernel_launch(void* const* d_in, const int* in_sizes, int n_in,
                              void* d_out, int out_size) {
    const float* x      = (const float*)d_in[0];
    const float* values = (const float*)d_in[1];
    const float* bias   = (const float*)d_in[2];
    const int*   rows   = (const int*)d_in[3];
    const int*   cols   = (const int*)d_in[4];
    float*       out    = (float*)d_out;
    const int nnz = in_sizes[1];

    static int smem_set = 0;
    if (!smem_set) {
        cudaFuncSetAttribute(gemm_kernel, cudaFuncAttributeMaxDynamicSharedMemorySize, SMEM_BYTES);
        smem_set = 1;
    }

    zero_wt_kernel<<<2048, 256>>>();
    scatter_kernel<<<(nnz + 255) / 256, 256>>>(values, rows, cols, nnz);
    conv_x_kernel<<<65536, 256>>>(x);
    gemm_kernel<<<dim3(OUT_F / 256, N_NODES / 128), 288, SMEM_BYTES>>>(bias, out);
}

// round 11
// speedup vs baseline: 1.0762x; 1.0762x over previous
#include <cuda_runtime.h>
#include <cuda_fp16.h>
#include <cstdint>

// ---------------------------------------------------------------------------
// Geometry
// ---------------------------------------------------------------------------
#define IN_F    2048
#define OUT_F   2048
#define N_NODES 65536
#define NKSLABS 32                       // K consumed in 64-half slabs
#define A_BLK   16384                    // 128 rows x 128B (64 halves)
#define B_BLK   32768                    // 256 rows x 128B
#define STAGES  4
#define STAGE_BYTES (A_BLK + B_BLK)      // 49152
#define SMEM_BYTES  (STAGES * STAGE_BYTES + 2048)

// ---------------------------------------------------------------------------
// Device scratch (allocation-free rule: static globals)
// ---------------------------------------------------------------------------
__device__ __align__(1024) unsigned char g_Wt[8 * NKSLABS * B_BLK];                 // 8 MB fp16 W, tiled+swizzled
__device__ __align__(1024) unsigned char g_Xt[(size_t)512 * NKSLABS * A_BLK];       // 256 MB fp16 x, tiled+swizzled

// ---------------------------------------------------------------------------
// PTX helpers (baseline PTX only)
// ---------------------------------------------------------------------------
__device__ __forceinline__ uint32_t smem_to_u32(const void* p) {
    uint32_t a;
    asm("{ .reg .u64 t; cvta.to.shared.u64 t, %1; cvt.u32.u64 %0, t; }" : "=r"(a) : "l"(p));
    return a;
}
#define MBARRIER_INIT(addr, cnt) \
    asm volatile("mbarrier.init.shared.b64 [%0], %1;" :: "r"((uint32_t)(addr)), "r"((uint32_t)(cnt)) : "memory")
#define MBARRIER_EXPECT_TX(addr, bytes) \
    asm volatile("mbarrier.arrive.expect_tx.shared.b64 _, [%0], %1;" :: "r"((uint32_t)(addr)), "r"((uint32_t)(bytes)) : "memory")
#define MBARRIER_ARRIVE(addr) \
    asm volatile("mbarrier.arrive.shared.b64 _, [%0];" :: "r"((uint32_t)(addr)) : "memory")
#define MBARRIER_WAIT_PARITY(addr, parity) do {                                            \
    uint32_t _m = (uint32_t)(addr); uint32_t _p = (uint32_t)(parity); uint32_t _d;         \
    asm volatile("{\n\t.reg .pred p;\n\t"                                                  \
        "mbarrier.try_wait.parity.acquire.cta.shared::cta.b64 p, [%1], %2;\n\t"            \
        "selp.b32 %0, 1, 0, p;\n\t}" : "=r"(_d) : "r"(_m), "r"(_p) : "memory");            \
    if (!_d) {                                                                             \
        asm volatile("{\n\t.reg .pred P1;\n\t"                                             \
            "WL_%=:\n\t"                                                                   \
            "mbarrier.try_wait.parity.acquire.cta.shared::cta.b64 P1, [%0], %1, 0x989680;\n\t" \
            "@P1 bra.uni WD_%=;\n\tbra.uni WL_%=;\n\tWD_%=:\n\t}"                          \
            :: "r"(_m), "r"(_p) : "memory");                                               \
    }                                                                                      \
} while (0)
#define FENCE_PROXY_ASYNC_SHARED_CTA() asm volatile("fence.proxy.async.shared::cta;" ::: "memory")
#define BULK_G2S(dst_smem, src_gmem, nbytes, mbar) \
    asm volatile("cp.async.bulk.shared::cluster.global.mbarrier::complete_tx::bytes [%0], [%1], %2, [%3];" \
                 :: "r"((uint32_t)(dst_smem)), "l"(src_gmem), "r"((uint32_t)(nbytes)), \
                    "r"((uint32_t)(mbar)) : "memory")
#define LDSM_X4(r, addr) \
    asm volatile("ldmatrix.sync.aligned.m8n8.x4.shared.b16 {%0,%1,%2,%3}, [%4];" \
                 : "=r"((r)[0]), "=r"((r)[1]), "=r"((r)[2]), "=r"((r)[3]) : "r"(addr))

__device__ __forceinline__ void mma16816(float* c, const uint32_t* a, const uint32_t* b) {
    asm volatile("mma.sync.aligned.m16n8k16.row.col.f32.f16.f16.f32 "
        "{%0,%1,%2,%3}, {%4,%5,%6,%7}, {%8,%9}, {%0,%1,%2,%3};"
        : "+f"(c[0]), "+f"(c[1]), "+f"(c[2]), "+f"(c[3])
        : "r"(a[0]), "r"(a[1]), "r"(a[2]), "r"(a[3]), "r"(b[0]), "r"(b[1]));
}

__device__ __forceinline__ uint32_t swz128(uint32_t off) { return off ^ ((off >> 3) & 0x70); }

// ---------------------------------------------------------------------------
// Preprocessing
// ---------------------------------------------------------------------------
__global__ void zero_wt_kernel() {
    int i = blockIdx.x * blockDim.x + threadIdx.x;          // 524288 float4s
    reinterpret_cast<float4*>(g_Wt)[i] = make_float4(0.f, 0.f, 0.f, 0.f);
}

// Scatter COO directly into fp16 tiled/swizzled W (sum semantics for dups)
__global__ void scatter_kernel(const float* __restrict__ vals, const int* __restrict__ rows,
                               const int* __restrict__ cols, int nnz) {
    int i = blockIdx.x * blockDim.x + threadIdx.x;
    if (i >= nnz) return;
    int n = rows[i], k = cols[i];
    uint32_t nt = n >> 8, r = n & 255, ks = k >> 6, c = k & 63;
    size_t off = (size_t)(nt * NKSLABS + ks) * B_BLK + swz128(r * 128 + c * 2);
    atomicAdd(reinterpret_cast<__half*>(g_Wt + off), __float2half(vals[i]));
}

// x fp32 -> fp16 tiled/swizzled; 16B store per thread (8 halves)
__global__ void conv_x_kernel(const float* __restrict__ x) {
    size_t e8 = (size_t)blockIdx.x * blockDim.x + threadIdx.x;  // 16.7M x 8-elem chunks
    int m = (int)(e8 >> 8);                                     // 256 chunks per row
    int k = ((int)e8 & 255) << 3;
    float4 v0 = reinterpret_cast<const float4*>(x)[e8 * 2];
    float4 v1 = reinterpret_cast<const float4*>(x)[e8 * 2 + 1];
    union { __half2 h[4]; uint4 u; } pk;
    pk.h[0] = __floats2half2_rn(v0.x, v0.y);
    pk.h[1] = __floats2half2_rn(v0.z, v0.w);
    pk.h[2] = __floats2half2_rn(v1.x, v1.y);
    pk.h[3] = __floats2half2_rn(v1.z, v1.w);
    uint32_t mt = (uint32_t)m >> 7, r = m & 127, ks = (uint32_t)k >> 6, c = k & 63;
    size_t off = ((size_t)mt * NKSLABS + ks) * A_BLK + swz128(r * 128 + c * 2);
    *reinterpret_cast<uint4*>(g_Xt + off) = pk.u;
}

// ---------------------------------------------------------------------------
// GEMM: CTA 128(M) x 256(N), 256 threads, warp tile 64x64 (warp grid 2M x 4N).
// Producer inline in tid 0 (R4 layout — keeps regs under the 256-thread cap).
// Cross-slab pipelining: FULL[s+1] wait at t==14, next-slab prologue at t==15.
// ---------------------------------------------------------------------------
__global__ void __launch_bounds__(256, 1)
gemm_kernel(const float* __restrict__ bias, float* __restrict__ out) {
    extern __shared__ __align__(16) unsigned char smem[];
    const uint32_t smem_u = smem_to_u32(smem);
    const uint32_t FULL   = smem_u;                              // 4 x 8B
    const uint32_t CONS   = smem_u + 32;                         // 4 x 8B
    const uint32_t base1k = (smem_u + 64 + 1023u) & ~1023u;      // stage data, 1KB aligned

    const int tid = threadIdx.x;
    const int w = tid >> 5, lane = tid & 31;
    const int wm = w >> 2, wn = w & 3;
    const int nsup = blockIdx.x;      // 0..7
    const int msup = blockIdx.y;      // 0..511

    if (tid == 0) {
        #pragma unroll
        for (int s = 0; s < STAGES; s++) {
            MBARRIER_INIT(FULL + 8 * s, 1);
            MBARRIER_INIT(CONS + 8 * s, 8);
        }
        FENCE_PROXY_ASYNC_SHARED_CTA();
    }
    __syncthreads();

    const unsigned char* Asrc = g_Xt + (size_t)msup * NKSLABS * A_BLK;
    const unsigned char* Bsrc = g_Wt + (size_t)nsup * NKSLABS * B_BLK;

    if (tid == 0) {
        #pragma unroll
        for (int s = 0; s < STAGES - 1; s++) {
            uint32_t sb = base1k + s * STAGE_BYTES;
            MBARRIER_EXPECT_TX(FULL + 8 * s, STAGE_BYTES);
            BULK_G2S(sb,         Asrc + (size_t)s * A_BLK, A_BLK, FULL + 8 * s);
            BULK_G2S(sb + A_BLK, Bsrc + (size_t)s * B_BLK, B_BLK, FULL + 8 * s);
        }
    }

    float acc[4][8][4];
    #pragma unroll
    for (int i = 0; i < 4; i++)
        #pragma unroll
        for (int j = 0; j < 8; j++)
            #pragma unroll
            for (int q = 0; q < 4; q++) acc[i][j][q] = 0.f;

    // ldmatrix per-lane address components
    const int jj = lane >> 3, r8 = lane & 7;
    const int a_row = (jj & 1) * 8 + r8;      // A: {m0-7,k0-7},{m8-15,k0-7},{m0-7,k8-15},{m8-15,k8-15}
    const int a_kb  = (jj >> 1) * 16;
    const int b_row = (jj >> 1) * 8 + r8;     // B: {n0-7,k0-7},{n0-7,k8-15},{n8-15,k0-7},{n8-15,k8-15}
    const int b_kb  = (jj & 1) * 16;
    const uint32_t a_base = (uint32_t)(wm * 64 + a_row) * 128 + a_kb;   // + ms*2048 + kk*32
    const uint32_t b_base = (uint32_t)(wn * 64 + b_row) * 128 + b_kb;   // + ng*2048 + kk*32

    uint32_t a[2][4][4], b[2][4];

    // slab-0 prologue
    MBARRIER_WAIT_PARITY(FULL + 0, 0);
    {
        const uint32_t Ast0 = base1k, Bst0 = base1k + A_BLK;
        #pragma unroll
        for (int ms = 0; ms < 4; ms++)
            LDSM_X4(a[0][ms], Ast0 + swz128(a_base + ms * 2048));
        LDSM_X4(b[0], Bst0 + swz128(b_base));
    }

    for (int s = 0; s < NKSLABS; s++) {
        const int st = s & 3;
        const uint32_t Ast = base1k + st * STAGE_BYTES;
        const uint32_t Bst = Ast + A_BLK;
        const int stn = (s + 1) & 3;
        const uint32_t AstN = base1k + stn * STAGE_BYTES;
        const uint32_t BstN = AstN + A_BLK;
        const int phN = ((s + 1) >> 2) & 1;
        const bool more = (s + 1 < NKSLABS);

        // producer (tid 0): refill stage s+3 after its prior consumers signalled
        if (tid == 0) {
            const int s2 = s + STAGES - 1;
            if (s2 < NKSLABS) {
                const int st2 = s2 & 3;
                const int k = s2 >> 2;
                if (k >= 1) MBARRIER_WAIT_PARITY(CONS + 8 * st2, (k - 1) & 1);
                uint32_t sb = base1k + st2 * STAGE_BYTES;
                MBARRIER_EXPECT_TX(FULL + 8 * st2, STAGE_BYTES);
                BULK_G2S(sb,         Asrc + (size_t)s2 * A_BLK, A_BLK, FULL + 8 * st2);
                BULK_G2S(sb + A_BLK, Bsrc + (size_t)s2 * B_BLK, B_BLK, FULL + 8 * st2);
            }
        }

        #pragma unroll
        for (int t = 0; t < 16; t++) {
            const int kk = t >> 2, ng = t & 3;
            const int cb = t & 1, ca = kk & 1;

            if (t < 15) {
                const int t1 = t + 1;
                LDSM_X4(b[cb ^ 1], Bst + swz128(b_base + (t1 & 3) * 2048 + (t1 >> 2) * 32));
            } else if (more) {
                // next-slab prologue (FULL[s+1] waited at t==14)
                LDSM_X4(b[cb ^ 1], BstN + swz128(b_base));
                #pragma unroll
                for (int ms = 0; ms < 4; ms++)
                    LDSM_X4(a[0][ms], AstN + swz128(a_base + ms * 2048));
            }
            if (ng == 0 && kk < 3) {
                #pragma unroll
                for (int ms = 0; ms < 4; ms++)
                    LDSM_X4(a[ca ^ 1][ms], Ast + swz128(a_base + ms * 2048 + (kk + 1) * 32));
            }
            #pragma unroll
            for (int ms = 0; ms < 4; ms++) {
                mma16816(acc[ms][2 * ng],     a[ca][ms], b[cb]);
                mma16816(acc[ms][2 * ng + 1], a[ca][ms], b[cb] + 2);
            }
            if (t == 14 && more) {
                // wait while ~8 pending MMA groups drain the tensor pipe
                MBARRIER_WAIT_PARITY(FULL + 8 * stn, phN);
            }
        }

        // this warp is done reading stage st (t==15 loads came from stage stn)
        if (lane == 0) MBARRIER_ARRIVE(CONS + 8 * st);
    }

    // ---- epilogue: acc + bias -> out ----
    const int g  = lane >> 2;
    const int cq = (lane & 3) * 2;
    const int n_cta = nsup * 256 + wn * 64;
    const int m_cta = msup * 128 + wm * 64;
    #pragma unroll
    for (int ms = 0; ms < 4; ms++) {
        const int m0 = m_cta + ms * 16 + g;
        #pragma unroll
        for (int ns = 0; ns < 8; ns++) {
            const int n = n_cta + ns * 8 + cq;
            const float2 bv = *reinterpret_cast<const float2*>(bias + n);
            float2 v0, v1;
            v0.x = acc[ms][ns][0] + bv.x; v0.y = acc[ms][ns][1] + bv.y;
            v1.x = acc[ms][ns][2] + bv.x; v1.y = acc[ms][ns][3] + bv.y;
            *reinterpret_cast<float2*>(out + (size_t)m0 * OUT_F + n)       = v0;
            *reinterpret_cast<float2*>(out + (size_t)(m0 + 8) * OUT_F + n) = v1;
        }
    }
}

// ---------------------------------------------------------------------------
// Host launch
// ---------------------------------------------------------------------------
extern "C" void kernel_launch(void* const* d_in, const int* in_sizes, int n_in,
                              void* d_out, int out_size) {
    const float* x      = (const float*)d_in[0];
    const float* values = (const float*)d_in[1];
    const float* bias   = (const float*)d_in[2];
    const int*   rows   = (const int*)d_in[3];
    const int*   cols   = (const int*)d_in[4];
    float*       out    = (float*)d_out;
    const int nnz = in_sizes[1];

    static int smem_set = 0;
    if (!smem_set) {
        cudaFuncSetAttribute(gemm_kernel, cudaFuncAttributeMaxDynamicSharedMemorySize, SMEM_BYTES);
        smem_set = 1;
    }

    zero_wt_kernel<<<2048, 256>>>();
    scatter_kernel<<<(nnz + 255) / 256, 256>>>(values, rows, cols, nnz);
    conv_x_kernel<<<65536, 256>>>(x);
    gemm_kernel<<<dim3(OUT_F / 256, N_NODES / 128), 256, SMEM_BYTES>>>(bias, out);
}

// round 12
// speedup vs baseline: 1.6664x; 1.5484x over previous
#include <cuda_runtime.h>
#include <cuda_fp16.h>
#include <cstdint>

// ---------------------------------------------------------------------------
// Geometry
// ---------------------------------------------------------------------------
#define IN_F    2048
#define OUT_F   2048
#define N_NODES 65536
#define NKSLABS 32                       // K consumed in 64-half slabs
#define A_BLK   16384                    // 128 rows x 128B (64 halves)
#define B_BLK   32768                    // 256 rows x 128B
#define STAGES  4
#define STAGE_BYTES (A_BLK + B_BLK)      // 49152
#define SMEM_BYTES  (STAGES * STAGE_BYTES + 2048)

// ---------------------------------------------------------------------------
// Device scratch (allocation-free rule: static globals)
// ---------------------------------------------------------------------------
__device__ __align__(1024) unsigned char g_Wt[8 * NKSLABS * B_BLK];                 // 8 MB fp16 W, tiled+swizzled
__device__ __align__(1024) unsigned char g_Xt[(size_t)512 * NKSLABS * A_BLK];       // 256 MB fp16 x, tiled+swizzled

// ---------------------------------------------------------------------------
// PTX helpers (baseline PTX only)
// ---------------------------------------------------------------------------
__device__ __forceinline__ uint32_t smem_to_u32(const void* p) {
    uint32_t a;
    asm("{ .reg .u64 t; cvta.to.shared.u64 t, %1; cvt.u32.u64 %0, t; }" : "=r"(a) : "l"(p));
    return a;
}
#define MBARRIER_INIT(addr, cnt) \
    asm volatile("mbarrier.init.shared.b64 [%0], %1;" :: "r"((uint32_t)(addr)), "r"((uint32_t)(cnt)) : "memory")
#define MBARRIER_EXPECT_TX(addr, bytes) \
    asm volatile("mbarrier.arrive.expect_tx.shared.b64 _, [%0], %1;" :: "r"((uint32_t)(addr)), "r"((uint32_t)(bytes)) : "memory")
#define MBARRIER_ARRIVE(addr) \
    asm volatile("mbarrier.arrive.shared.b64 _, [%0];" :: "r"((uint32_t)(addr)) : "memory")
#define MBARRIER_WAIT_PARITY(addr, parity) do {                                            \
    uint32_t _m = (uint32_t)(addr); uint32_t _p = (uint32_t)(parity); uint32_t _d;         \
    asm volatile("{\n\t.reg .pred p;\n\t"                                                  \
        "mbarrier.try_wait.parity.acquire.cta.shared::cta.b64 p, [%1], %2;\n\t"            \
        "selp.b32 %0, 1, 0, p;\n\t}" : "=r"(_d) : "r"(_m), "r"(_p) : "memory");            \
    if (!_d) {                                                                             \
        asm volatile("{\n\t.reg .pred P1;\n\t"                                             \
            "WL_%=:\n\t"                                                                   \
            "mbarrier.try_wait.parity.acquire.cta.shared::cta.b64 P1, [%0], %1, 0x989680;\n\t" \
            "@P1 bra.uni WD_%=;\n\tbra.uni WL_%=;\n\tWD_%=:\n\t}"                          \
            :: "r"(_m), "r"(_p) : "memory");                                               \
    }                                                                                      \
} while (0)
// relaxed: producer-only (post-wait accesses are async-proxy TMA, self-ordered)
#define MBARRIER_WAIT_PARITY_RELAXED(addr, parity) do {                                    \
    uint32_t _m = (uint32_t)(addr); uint32_t _p = (uint32_t)(parity); uint32_t _d;         \
    asm volatile("{\n\t.reg .pred p;\n\t"                                                  \
        "mbarrier.try_wait.parity.relaxed.cta.shared::cta.b64 p, [%1], %2, 0x989680;\n\t"  \
        "selp.b32 %0, 1, 0, p;\n\t}" : "=r"(_d) : "r"(_m), "r"(_p) : "memory");            \
    if (!_d) {                                                                             \
        asm volatile("{\n\t.reg .pred P1;\n\t"                                             \
            "WL_%=:\n\t"                                                                   \
            "mbarrier.try_wait.parity.relaxed.cta.shared::cta.b64 P1, [%0], %1, 0x989680;\n\t" \
            "@P1 bra.uni WD_%=;\n\tbra.uni WL_%=;\n\tWD_%=:\n\t}"                          \
            :: "r"(_m), "r"(_p) : "memory");                                               \
    }                                                                                      \
} while (0)
#define FENCE_PROXY_ASYNC_SHARED_CTA() asm volatile("fence.proxy.async.shared::cta;" ::: "memory")
#define BULK_G2S(dst_smem, src_gmem, nbytes, mbar) \
    asm volatile("cp.async.bulk.shared::cluster.global.mbarrier::complete_tx::bytes [%0], [%1], %2, [%3];" \
                 :: "r"((uint32_t)(dst_smem)), "l"(src_gmem), "r"((uint32_t)(nbytes)), \
                    "r"((uint32_t)(mbar)) : "memory")
#define LDSM_X4(r, addr) \
    asm volatile("ldmatrix.sync.aligned.m8n8.x4.shared.b16 {%0,%1,%2,%3}, [%4];" \
                 : "=r"((r)[0]), "=r"((r)[1]), "=r"((r)[2]), "=r"((r)[3]) : "r"(addr))

__device__ __forceinline__ void mma16816(float* c, const uint32_t* a, const uint32_t* b) {
    asm volatile("mma.sync.aligned.m16n8k16.row.col.f32.f16.f16.f32 "
        "{%0,%1,%2,%3}, {%4,%5,%6,%7}, {%8,%9}, {%0,%1,%2,%3};"
        : "+f"(c[0]), "+f"(c[1]), "+f"(c[2]), "+f"(c[3])
        : "r"(a[0]), "r"(a[1]), "r"(a[2]), "r"(a[3]), "r"(b[0]), "r"(b[1]));
}

__device__ __forceinline__ uint32_t swz128(uint32_t off) { return off ^ ((off >> 3) & 0x70); }

// ---------------------------------------------------------------------------
// Preprocessing
// ---------------------------------------------------------------------------
__global__ void zero_wt_kernel() {
    int i = blockIdx.x * blockDim.x + threadIdx.x;          // 524288 float4s
    reinterpret_cast<float4*>(g_Wt)[i] = make_float4(0.f, 0.f, 0.f, 0.f);
}

// Scatter COO directly into fp16 tiled/swizzled W (sum semantics for dups)
__global__ void scatter_kernel(const float* __restrict__ vals, const int* __restrict__ rows,
                               const int* __restrict__ cols, int nnz) {
    int i = blockIdx.x * blockDim.x + threadIdx.x;
    if (i >= nnz) return;
    int n = rows[i], k = cols[i];
    uint32_t nt = n >> 8, r = n & 255, ks = k >> 6, c = k & 63;
    size_t off = (size_t)(nt * NKSLABS + ks) * B_BLK + swz128(r * 128 + c * 2);
    atomicAdd(reinterpret_cast<__half*>(g_Wt + off), __float2half(vals[i]));
}

// x fp32 -> fp16 tiled/swizzled; 16B store per thread (8 halves)
__global__ void conv_x_kernel(const float* __restrict__ x) {
    size_t e8 = (size_t)blockIdx.x * blockDim.x + threadIdx.x;  // 16.7M x 8-elem chunks
    int m = (int)(e8 >> 8);                                     // 256 chunks per row
    int k = ((int)e8 & 255) << 3;
    float4 v0 = reinterpret_cast<const float4*>(x)[e8 * 2];
    float4 v1 = reinterpret_cast<const float4*>(x)[e8 * 2 + 1];
    union { __half2 h[4]; uint4 u; } pk;
    pk.h[0] = __floats2half2_rn(v0.x, v0.y);
    pk.h[1] = __floats2half2_rn(v0.z, v0.w);
    pk.h[2] = __floats2half2_rn(v1.x, v1.y);
    pk.h[3] = __floats2half2_rn(v1.z, v1.w);
    uint32_t mt = (uint32_t)m >> 7, r = m & 127, ks = (uint32_t)k >> 6, c = k & 63;
    size_t off = ((size_t)mt * NKSLABS + ks) * A_BLK + swz128(r * 128 + c * 2);
    *reinterpret_cast<uint4*>(g_Xt + off) = pk.u;
}

// ---------------------------------------------------------------------------
// GEMM: CTA 128(M) x 256(N), 256 threads, warp tile 64x64 (warp grid 2M x 4N).
// Producer duty SPREAD across warps 0-3 (stage st refilled by warp st, lane 0)
// so no single warp is a per-slab straggler. Cross-slab pipelining: FULL[s+1]
// wait at t==13, next-slab prologue at t==15.
// ---------------------------------------------------------------------------
__global__ void __launch_bounds__(256, 1)
gemm_kernel(const float* __restrict__ bias, float* __restrict__ out) {
    extern __shared__ __align__(16) unsigned char smem[];
    const uint32_t smem_u = smem_to_u32(smem);
    const uint32_t FULL   = smem_u;                              // 4 x 8B
    const uint32_t CONS   = smem_u + 32;                         // 4 x 8B
    const uint32_t base1k = (smem_u + 64 + 1023u) & ~1023u;      // stage data, 1KB aligned

    const int tid = threadIdx.x;
    const int w = tid >> 5, lane = tid & 31;
    const int wm = w >> 2, wn = w & 3;
    const int nsup = blockIdx.x;      // 0..7
    const int msup = blockIdx.y;      // 0..511

    if (tid == 0) {
        #pragma unroll
        for (int s = 0; s < STAGES; s++) {
            MBARRIER_INIT(FULL + 8 * s, 1);
            MBARRIER_INIT(CONS + 8 * s, 8);
        }
        FENCE_PROXY_ASYNC_SHARED_CTA();
    }
    __syncthreads();

    const unsigned char* Asrc = g_Xt + (size_t)msup * NKSLABS * A_BLK;
    const unsigned char* Bsrc = g_Wt + (size_t)nsup * NKSLABS * B_BLK;

    if (tid == 0) {
        #pragma unroll
        for (int s = 0; s < STAGES - 1; s++) {
            uint32_t sb = base1k + s * STAGE_BYTES;
            MBARRIER_EXPECT_TX(FULL + 8 * s, STAGE_BYTES);
            BULK_G2S(sb,         Asrc + (size_t)s * A_BLK, A_BLK, FULL + 8 * s);
            BULK_G2S(sb + A_BLK, Bsrc + (size_t)s * B_BLK, B_BLK, FULL + 8 * s);
        }
    }

    float acc[4][8][4];
    #pragma unroll
    for (int i = 0; i < 4; i++)
        #pragma unroll
        for (int j = 0; j < 8; j++)
            #pragma unroll
            for (int q = 0; q < 4; q++) acc[i][j][q] = 0.f;

    // ldmatrix per-lane address components
    const int jj = lane >> 3, r8 = lane & 7;
    const int a_row = (jj & 1) * 8 + r8;      // A: {m0-7,k0-7},{m8-15,k0-7},{m0-7,k8-15},{m8-15,k8-15}
    const int a_kb  = (jj >> 1) * 16;
    const int b_row = (jj >> 1) * 8 + r8;     // B: {n0-7,k0-7},{n0-7,k8-15},{n8-15,k0-7},{n8-15,k8-15}
    const int b_kb  = (jj & 1) * 16;
    const uint32_t a_base = (uint32_t)(wm * 64 + a_row) * 128 + a_kb;   // + ms*2048 + kk*32
    const uint32_t b_base = (uint32_t)(wn * 64 + b_row) * 128 + b_kb;   // + ng*2048 + kk*32

    uint32_t a[2][4][4], b[2][4];

    // slab-0 prologue
    MBARRIER_WAIT_PARITY(FULL + 0, 0);
    {
        const uint32_t Ast0 = base1k, Bst0 = base1k + A_BLK;
        #pragma unroll
        for (int ms = 0; ms < 4; ms++)
            LDSM_X4(a[0][ms], Ast0 + swz128(a_base + ms * 2048));
        LDSM_X4(b[0], Bst0 + swz128(b_base));
    }

    for (int s = 0; s < NKSLABS; s++) {
        const int st = s & 3;
        const uint32_t Ast = base1k + st * STAGE_BYTES;
        const uint32_t Bst = Ast + A_BLK;
        const int stn = (s + 1) & 3;
        const uint32_t AstN = base1k + stn * STAGE_BYTES;
        const uint32_t BstN = AstN + A_BLK;
        const int phN = ((s + 1) >> 2) & 1;
        const bool more = (s + 1 < NKSLABS);

        // producer: stage st2 refilled by warp st2 (lane 0) — duty rotates so
        // no single warp pays the producer stall every slab
        {
            const int s2 = s + STAGES - 1;
            const int st2 = s2 & 3;
            if (s2 < NKSLABS && w == st2 && lane == 0) {
                const int k = s2 >> 2;
                if (k >= 1) MBARRIER_WAIT_PARITY_RELAXED(CONS + 8 * st2, (k - 1) & 1);
                uint32_t sb = base1k + st2 * STAGE_BYTES;
                MBARRIER_EXPECT_TX(FULL + 8 * st2, STAGE_BYTES);
                BULK_G2S(sb,         Asrc + (size_t)s2 * A_BLK, A_BLK, FULL + 8 * st2);
                BULK_G2S(sb + A_BLK, Bsrc + (size_t)s2 * B_BLK, B_BLK, FULL + 8 * st2);
            }
        }

        #pragma unroll
        for (int t = 0; t < 16; t++) {
            const int kk = t >> 2, ng = t & 3;
            const int cb = t & 1, ca = kk & 1;

            if (t < 15) {
                const int t1 = t + 1;
                LDSM_X4(b[cb ^ 1], Bst + swz128(b_base + (t1 & 3) * 2048 + (t1 >> 2) * 32));
            } else if (more) {
                // next-slab prologue (FULL[s+1] waited at t==13)
                LDSM_X4(b[cb ^ 1], BstN + swz128(b_base));
                #pragma unroll
                for (int ms = 0; ms < 4; ms++)
                    LDSM_X4(a[0][ms], AstN + swz128(a_base + ms * 2048));
            }
            if (ng == 0 && kk < 3) {
                #pragma unroll
                for (int ms = 0; ms < 4; ms++)
                    LDSM_X4(a[ca ^ 1][ms], Ast + swz128(a_base + ms * 2048 + (kk + 1) * 32));
            }
            #pragma unroll
            for (int ms = 0; ms < 4; ms++) {
                mma16816(acc[ms][2 * ng],     a[ca][ms], b[cb]);
                mma16816(acc[ms][2 * ng + 1], a[ca][ms], b[cb] + 2);
            }
            if (t == 13 && more) {
                // wait while ~16 pending MMA groups (2 warps/SMSP) drain
                MBARRIER_WAIT_PARITY(FULL + 8 * stn, phN);
            }
        }

        // this warp is done reading stage st (t==15 loads came from stage stn)
        if (lane == 0) MBARRIER_ARRIVE(CONS + 8 * st);
    }

    // ---- epilogue: acc + bias -> out ----
    const int g  = lane >> 2;
    const int cq = (lane & 3) * 2;
    const int n_cta = nsup * 256 + wn * 64;
    const int m_cta = msup * 128 + wm * 64;
    #pragma unroll
    for (int ms = 0; ms < 4; ms++) {
        const int m0 = m_cta + ms * 16 + g;
        #pragma unroll
        for (int ns = 0; ns < 8; ns++) {
            const int n = n_cta + ns * 8 + cq;
            const float2 bv = *reinterpret_cast<const float2*>(bias + n);
            float2 v0, v1;
            v0.x = acc[ms][ns][0] + bv.x; v0.y = acc[ms][ns][1] + bv.y;
            v1.x = acc[ms][ns][2] + bv.x; v1.y = acc[ms][ns][3] + bv.y;
            *reinterpret_cast<float2*>(out + (size_t)m0 * OUT_F + n)       = v0;
            *reinterpret_cast<float2*>(out + (size_t)(m0 + 8) * OUT_F + n) = v1;
        }
    }
}

// ---------------------------------------------------------------------------
// Host launch
// ---------------------------------------------------------------------------
extern "C" void kernel_launch(void* const* d_in, const int* in_sizes, int n_in,
                              void* d_out, int out_size) {
    const float* x      = (const float*)d_in[0];
    const float* values = (const float*)d_in[1];
    const float* bias   = (const float*)d_in[2];
    const int*   rows   = (const int*)d_in[3];
    const int*   cols   = (const int*)d_in[4];
    float*       out    = (float*)d_out;
    const int nnz = in_sizes[1];

    cudaFuncSetAttribute(gemm_kernel, cudaFuncAttributeMaxDynamicSharedMemorySize, SMEM_BYTES);

    zero_wt_kernel<<<2048, 256>>>();
    scatter_kernel<<<(nnz + 255) / 256, 256>>>(values, rows, cols, nnz);
    conv_x_kernel<<<65536, 256>>>(x);
    gemm_kernel<<<dim3(OUT_F / 256, N_NODES / 128), 256, SMEM_BYTES>>>(bias, out);
}